// round 1
// baseline (speedup 1.0000x reference)
#include <cuda_runtime.h>

// ---------------------------------------------------------------------------
// MultiHeadAttention: out = proj_o( softmax_causal( (xWq^T+bq)(xWk^T+bk)^T / 8 ) (xWv^T+bv) )
// B=4, S=2048, D=1024, H=16, DK=64.  All fp32.
//
// Round 1: robust FFMA implementation.
//   - sgemm_nt_bias: C[M,N] = A[M,K] @ W[N,K]^T + bias  (128x128x8 tiles, 8x8/thread)
//   - attn_kernel:  flash attention, 64-query tile/block, causal tile skip,
//                   q/k/v kept in [B,S,H*DK] layout (no transposes).
// ---------------------------------------------------------------------------

#define B_SZ   4
#define S_LEN  2048
#define D_DIM  1024
#define NH     16
#define DKH    64
#define NROWS  (B_SZ * S_LEN)          // 8192

// Scratch (static device globals -- allocation rules forbid cudaMalloc)
__device__ float g_q[NROWS * D_DIM];
__device__ float g_k[NROWS * D_DIM];
__device__ float g_v[NROWS * D_DIM];
__device__ float g_vals[NROWS * D_DIM];

// ---------------------------------------------------------------------------
// SGEMM:  C = A @ W^T + bias.   A:[M,K] row-major, W:[N,K] row-major.
// Block tile 128x128, K-tile 8, 256 threads, 8x8 outputs per thread.
// ---------------------------------------------------------------------------
__global__ void __launch_bounds__(256)
sgemm_nt_bias(const float* __restrict__ A, const float* __restrict__ W,
              const float* __restrict__ bias, float* __restrict__ C,
              int M, int N, int K)
{
    __shared__ float As[8][128];
    __shared__ float Ws[8][128];

    const int tid = threadIdx.x;
    const int bm  = blockIdx.y * 128;
    const int bn  = blockIdx.x * 128;
    const int tx  = tid & 15;          // 0..15  (col group)
    const int ty  = tid >> 4;          // 0..15  (row group)
    const int lrow = tid >> 1;         // 0..127 (loader row)
    const int lk4  = (tid & 1) << 2;   // 0 or 4 (loader k-offset)

    const float* Ap = A + (size_t)(bm + lrow) * K + lk4;
    const float* Wp = W + (size_t)(bn + lrow) * K + lk4;

    float acc[8][8];
    #pragma unroll
    for (int i = 0; i < 8; i++)
        #pragma unroll
        for (int j = 0; j < 8; j++) acc[i][j] = 0.f;

    for (int k0 = 0; k0 < K; k0 += 8) {
        float4 a4 = *(const float4*)(Ap + k0);
        float4 w4 = *(const float4*)(Wp + k0);
        As[lk4+0][lrow] = a4.x; As[lk4+1][lrow] = a4.y;
        As[lk4+2][lrow] = a4.z; As[lk4+3][lrow] = a4.w;
        Ws[lk4+0][lrow] = w4.x; Ws[lk4+1][lrow] = w4.y;
        Ws[lk4+2][lrow] = w4.z; Ws[lk4+3][lrow] = w4.w;
        __syncthreads();

        #pragma unroll
        for (int kk = 0; kk < 8; kk++) {
            float4 a0 = *(const float4*)(&As[kk][ty*8]);
            float4 a1 = *(const float4*)(&As[kk][ty*8+4]);
            float4 w0 = *(const float4*)(&Ws[kk][tx*8]);
            float4 w1 = *(const float4*)(&Ws[kk][tx*8+4]);
            float af[8] = {a0.x,a0.y,a0.z,a0.w,a1.x,a1.y,a1.z,a1.w};
            float wf[8] = {w0.x,w0.y,w0.z,w0.w,w1.x,w1.y,w1.z,w1.w};
            #pragma unroll
            for (int i = 0; i < 8; i++)
                #pragma unroll
                for (int j = 0; j < 8; j++)
                    acc[i][j] = fmaf(af[i], wf[j], acc[i][j]);
        }
        __syncthreads();
    }

    float bfrag[8];
    #pragma unroll
    for (int j = 0; j < 8; j++) bfrag[j] = bias[bn + tx*8 + j];

    #pragma unroll
    for (int i = 0; i < 8; i++) {
        const size_t row = (size_t)(bm + ty*8 + i);
        float* cp = C + row * N + bn + tx*8;
        float4 o0 = {acc[i][0]+bfrag[0], acc[i][1]+bfrag[1],
                     acc[i][2]+bfrag[2], acc[i][3]+bfrag[3]};
        float4 o1 = {acc[i][4]+bfrag[4], acc[i][5]+bfrag[5],
                     acc[i][6]+bfrag[6], acc[i][7]+bfrag[7]};
        *(float4*)cp     = o0;
        *(float4*)(cp+4) = o1;
    }
}

// ---------------------------------------------------------------------------
// Flash attention, causal.  One block = 64 query rows of one (b,h).
// 256 threads: thread t -> query row r = t/4, group g = t%4.
//   scores:  thread owns j in {g, g+4, ..., g+60}  (16 scores)
//   output:  thread owns dk float4-chunks {g, g+4, g+8, g+12} (16 floats)
// Row stride in smem = 68 floats -> all LDS.128 patterns bank-conflict-free.
// q/k/v layout: [B,S,H*DK]; head h's row s at base + s*D + h*64.
// ---------------------------------------------------------------------------
#define QT     64
#define PADF   68
#define ATTN_SMEM (4 * QT * PADF * (int)sizeof(float))   // 69632 B

__global__ void __launch_bounds__(256)
attn_kernel()
{
    extern __shared__ float sm[];
    float* Qs = sm;
    float* Ks = Qs + QT*PADF;
    float* Vs = Ks + QT*PADF;
    float* Ps = Vs + QT*PADF;

    const int tid = threadIdx.x;
    const int qt  = blockIdx.x;
    const int bh  = blockIdx.y;
    const int b   = bh >> 4;
    const int h   = bh & 15;
    const size_t base = (size_t)b * S_LEN * D_DIM + (size_t)h * DKH;
    const int q0 = qt * QT;

    // load Q tile (64 rows x 64 floats)
    for (int idx = tid; idx < QT*16; idx += 256) {
        int row = idx >> 4, c = (idx & 15) << 2;
        *(float4*)(Qs + row*PADF + c) =
            *(const float4*)(g_q + base + (size_t)(q0+row)*D_DIM + c);
    }

    const int r = tid >> 2;
    const int g = tid & 3;
    float acc[16];
    #pragma unroll
    for (int i = 0; i < 16; i++) acc[i] = 0.f;
    float m_run = -1e30f, l_run = 0.f;

    for (int jt = 0; jt <= qt; jt++) {
        __syncthreads();   // everyone done with previous Ks/Vs
        const int k0 = jt * QT;
        for (int idx = tid; idx < QT*16; idx += 256) {
            int row = idx >> 4, c = (idx & 15) << 2;
            *(float4*)(Ks + row*PADF + c) =
                *(const float4*)(g_k + base + (size_t)(k0+row)*D_DIM + c);
            *(float4*)(Vs + row*PADF + c) =
                *(const float4*)(g_v + base + (size_t)(k0+row)*D_DIM + c);
        }
        __syncthreads();

        // ---- scores: s[i] = Q[r] . K[g+4i] ----
        float s[16];
        #pragma unroll
        for (int i = 0; i < 16; i++) s[i] = 0.f;
        #pragma unroll
        for (int d4 = 0; d4 < 16; d4++) {
            const float4 q4 = *(const float4*)(Qs + r*PADF + d4*4);
            #pragma unroll
            for (int i = 0; i < 16; i++) {
                const float4 k4 = *(const float4*)(Ks + (g + 4*i)*PADF + d4*4);
                s[i] = fmaf(q4.x, k4.x,
                       fmaf(q4.y, k4.y,
                       fmaf(q4.z, k4.z,
                       fmaf(q4.w, k4.w, s[i]))));
            }
        }

        // ---- scale + causal mask + online softmax ----
        float mt = -1e30f;
        const bool diag = (jt == qt);
        #pragma unroll
        for (int i = 0; i < 16; i++) {
            s[i] *= 0.125f;                       // 1/sqrt(64)
            if (diag && (g + 4*i) > r) s[i] = -1e30f;
            mt = fmaxf(mt, s[i]);
        }
        mt = fmaxf(mt, __shfl_xor_sync(0xffffffffu, mt, 1));
        mt = fmaxf(mt, __shfl_xor_sync(0xffffffffu, mt, 2));
        const float m_new = fmaxf(m_run, mt);
        const float alpha = __expf(m_run - m_new);

        float psum = 0.f;
        #pragma unroll
        for (int i = 0; i < 16; i++) {
            const float p = __expf(s[i] - m_new);
            psum += p;
            Ps[r*PADF + g + 4*i] = p;
        }
        psum += __shfl_xor_sync(0xffffffffu, psum, 1);
        psum += __shfl_xor_sync(0xffffffffu, psum, 2);
        l_run = l_run * alpha + psum;
        m_run = m_new;
        #pragma unroll
        for (int i = 0; i < 16; i++) acc[i] *= alpha;

        __syncwarp();   // Ps for row r written only by this warp's 4 threads

        // ---- acc += P[r][:] @ V ----
        #pragma unroll 4
        for (int j = 0; j < QT; j++) {
            const float p = Ps[r*PADF + j];
            #pragma unroll
            for (int mI = 0; mI < 4; mI++) {
                const float4 v4 = *(const float4*)(Vs + j*PADF + (g + 4*mI)*4);
                acc[mI*4+0] = fmaf(p, v4.x, acc[mI*4+0]);
                acc[mI*4+1] = fmaf(p, v4.y, acc[mI*4+1]);
                acc[mI*4+2] = fmaf(p, v4.z, acc[mI*4+2]);
                acc[mI*4+3] = fmaf(p, v4.w, acc[mI*4+3]);
            }
        }
    }

    const float inv = 1.f / l_run;
    float* op = g_vals + base + (size_t)(q0 + r) * D_DIM;
    #pragma unroll
    for (int mI = 0; mI < 4; mI++) {
        float4 o;
        o.x = acc[mI*4+0]*inv; o.y = acc[mI*4+1]*inv;
        o.z = acc[mI*4+2]*inv; o.w = acc[mI*4+3]*inv;
        *(float4*)(op + (g + 4*mI)*4) = o;
    }
}

// ---------------------------------------------------------------------------
// kernel_launch
// inputs: x, mask, Wq, bq, Wk, bk, Wv, bv, Wo, bo   (mask ignored; causal known)
// ---------------------------------------------------------------------------
extern "C" void kernel_launch(void* const* d_in, const int* in_sizes, int n_in,
                              void* d_out, int out_size)
{
    (void)in_sizes; (void)n_in; (void)out_size;
    const float* x  = (const float*)d_in[0];
    const float* Wq = (const float*)d_in[2];
    const float* bq = (const float*)d_in[3];
    const float* Wk = (const float*)d_in[4];
    const float* bk = (const float*)d_in[5];
    const float* Wv = (const float*)d_in[6];
    const float* bv = (const float*)d_in[7];
    const float* Wo = (const float*)d_in[8];
    const float* bo = (const float*)d_in[9];
    float* out = (float*)d_out;

    float *qp, *kp, *vp, *valsp;
    cudaGetSymbolAddress((void**)&qp,    g_q);
    cudaGetSymbolAddress((void**)&kp,    g_k);
    cudaGetSymbolAddress((void**)&vp,    g_v);
    cudaGetSymbolAddress((void**)&valsp, g_vals);

    cudaFuncSetAttribute(attn_kernel,
                         cudaFuncAttributeMaxDynamicSharedMemorySize, ATTN_SMEM);

    dim3 blk(256);
    dim3 gP(D_DIM/128, NROWS/128);         // (8, 64)
    sgemm_nt_bias<<<gP, blk>>>(x, Wq, bq, qp, NROWS, D_DIM, D_DIM);
    sgemm_nt_bias<<<gP, blk>>>(x, Wk, bk, kp, NROWS, D_DIM, D_DIM);
    sgemm_nt_bias<<<gP, blk>>>(x, Wv, bv, vp, NROWS, D_DIM, D_DIM);

    dim3 gA(S_LEN/QT, B_SZ*NH);            // (32, 64)
    attn_kernel<<<gA, blk, ATTN_SMEM>>>();

    sgemm_nt_bias<<<gP, blk>>>(valsp, Wo, bo, out, NROWS, D_DIM, D_DIM);
}

// round 2
// speedup vs baseline: 1.0041x; 1.0041x over previous
#include <cuda_runtime.h>

// ---------------------------------------------------------------------------
// MultiHeadAttention: out = proj_o( softmax_causal( (xWq^T+bq)(xWk^T+bk)^T / 8 ) (xWv^T+bv) )
// B=4, S=2048, D=1024, H=16, DK=64.  All fp32.
//
// Round 1: robust FFMA implementation.
//   - sgemm_nt_bias: C[M,N] = A[M,K] @ W[N,K]^T + bias  (128x128x8 tiles, 8x8/thread)
//   - attn_kernel:  flash attention, 64-query tile/block, causal tile skip,
//                   q/k/v kept in [B,S,H*DK] layout (no transposes).
// ---------------------------------------------------------------------------

#define B_SZ   4
#define S_LEN  2048
#define D_DIM  1024
#define NH     16
#define DKH    64
#define NROWS  (B_SZ * S_LEN)          // 8192

// Scratch (static device globals -- allocation rules forbid cudaMalloc)
__device__ float g_q[NROWS * D_DIM];
__device__ float g_k[NROWS * D_DIM];
__device__ float g_v[NROWS * D_DIM];
__device__ float g_vals[NROWS * D_DIM];

// ---------------------------------------------------------------------------
// SGEMM:  C = A @ W^T + bias.   A:[M,K] row-major, W:[N,K] row-major.
// Block tile 128x128, K-tile 8, 256 threads, 8x8 outputs per thread.
// ---------------------------------------------------------------------------
__global__ void __launch_bounds__(256)
sgemm_nt_bias(const float* __restrict__ A, const float* __restrict__ W,
              const float* __restrict__ bias, float* __restrict__ C,
              int M, int N, int K)
{
    __shared__ float As[8][128];
    __shared__ float Ws[8][128];

    const int tid = threadIdx.x;
    const int bm  = blockIdx.y * 128;
    const int bn  = blockIdx.x * 128;
    const int tx  = tid & 15;          // 0..15  (col group)
    const int ty  = tid >> 4;          // 0..15  (row group)
    const int lrow = tid >> 1;         // 0..127 (loader row)
    const int lk4  = (tid & 1) << 2;   // 0 or 4 (loader k-offset)

    const float* Ap = A + (size_t)(bm + lrow) * K + lk4;
    const float* Wp = W + (size_t)(bn + lrow) * K + lk4;

    float acc[8][8];
    #pragma unroll
    for (int i = 0; i < 8; i++)
        #pragma unroll
        for (int j = 0; j < 8; j++) acc[i][j] = 0.f;

    for (int k0 = 0; k0 < K; k0 += 8) {
        float4 a4 = *(const float4*)(Ap + k0);
        float4 w4 = *(const float4*)(Wp + k0);
        As[lk4+0][lrow] = a4.x; As[lk4+1][lrow] = a4.y;
        As[lk4+2][lrow] = a4.z; As[lk4+3][lrow] = a4.w;
        Ws[lk4+0][lrow] = w4.x; Ws[lk4+1][lrow] = w4.y;
        Ws[lk4+2][lrow] = w4.z; Ws[lk4+3][lrow] = w4.w;
        __syncthreads();

        #pragma unroll
        for (int kk = 0; kk < 8; kk++) {
            float4 a0 = *(const float4*)(&As[kk][ty*8]);
            float4 a1 = *(const float4*)(&As[kk][ty*8+4]);
            float4 w0 = *(const float4*)(&Ws[kk][tx*8]);
            float4 w1 = *(const float4*)(&Ws[kk][tx*8+4]);
            float af[8] = {a0.x,a0.y,a0.z,a0.w,a1.x,a1.y,a1.z,a1.w};
            float wf[8] = {w0.x,w0.y,w0.z,w0.w,w1.x,w1.y,w1.z,w1.w};
            #pragma unroll
            for (int i = 0; i < 8; i++)
                #pragma unroll
                for (int j = 0; j < 8; j++)
                    acc[i][j] = fmaf(af[i], wf[j], acc[i][j]);
        }
        __syncthreads();
    }

    float bfrag[8];
    #pragma unroll
    for (int j = 0; j < 8; j++) bfrag[j] = bias[bn + tx*8 + j];

    #pragma unroll
    for (int i = 0; i < 8; i++) {
        const size_t row = (size_t)(bm + ty*8 + i);
        float* cp = C + row * N + bn + tx*8;
        float4 o0 = {acc[i][0]+bfrag[0], acc[i][1]+bfrag[1],
                     acc[i][2]+bfrag[2], acc[i][3]+bfrag[3]};
        float4 o1 = {acc[i][4]+bfrag[4], acc[i][5]+bfrag[5],
                     acc[i][6]+bfrag[6], acc[i][7]+bfrag[7]};
        *(float4*)cp     = o0;
        *(float4*)(cp+4) = o1;
    }
}

// ---------------------------------------------------------------------------
// Flash attention, causal.  One block = 64 query rows of one (b,h).
// 256 threads: thread t -> query row r = t/4, group g = t%4.
//   scores:  thread owns j in {g, g+4, ..., g+60}  (16 scores)
//   output:  thread owns dk float4-chunks {g, g+4, g+8, g+12} (16 floats)
// Row stride in smem = 68 floats -> all LDS.128 patterns bank-conflict-free.
// q/k/v layout: [B,S,H*DK]; head h's row s at base + s*D + h*64.
// ---------------------------------------------------------------------------
#define QT     64
#define PADF   68
#define ATTN_SMEM (4 * QT * PADF * (int)sizeof(float))   // 69632 B

__global__ void __launch_bounds__(256)
attn_kernel()
{
    extern __shared__ float sm[];
    float* Qs = sm;
    float* Ks = Qs + QT*PADF;
    float* Vs = Ks + QT*PADF;
    float* Ps = Vs + QT*PADF;

    const int tid = threadIdx.x;
    const int qt  = blockIdx.x;
    const int bh  = blockIdx.y;
    const int b   = bh >> 4;
    const int h   = bh & 15;
    const size_t base = (size_t)b * S_LEN * D_DIM + (size_t)h * DKH;
    const int q0 = qt * QT;

    // load Q tile (64 rows x 64 floats)
    for (int idx = tid; idx < QT*16; idx += 256) {
        int row = idx >> 4, c = (idx & 15) << 2;
        *(float4*)(Qs + row*PADF + c) =
            *(const float4*)(g_q + base + (size_t)(q0+row)*D_DIM + c);
    }

    const int r = tid >> 2;
    const int g = tid & 3;
    float acc[16];
    #pragma unroll
    for (int i = 0; i < 16; i++) acc[i] = 0.f;
    float m_run = -1e30f, l_run = 0.f;

    for (int jt = 0; jt <= qt; jt++) {
        __syncthreads();   // everyone done with previous Ks/Vs
        const int k0 = jt * QT;
        for (int idx = tid; idx < QT*16; idx += 256) {
            int row = idx >> 4, c = (idx & 15) << 2;
            *(float4*)(Ks + row*PADF + c) =
                *(const float4*)(g_k + base + (size_t)(k0+row)*D_DIM + c);
            *(float4*)(Vs + row*PADF + c) =
                *(const float4*)(g_v + base + (size_t)(k0+row)*D_DIM + c);
        }
        __syncthreads();

        // ---- scores: s[i] = Q[r] . K[g+4i] ----
        float s[16];
        #pragma unroll
        for (int i = 0; i < 16; i++) s[i] = 0.f;
        #pragma unroll
        for (int d4 = 0; d4 < 16; d4++) {
            const float4 q4 = *(const float4*)(Qs + r*PADF + d4*4);
            #pragma unroll
            for (int i = 0; i < 16; i++) {
                const float4 k4 = *(const float4*)(Ks + (g + 4*i)*PADF + d4*4);
                s[i] = fmaf(q4.x, k4.x,
                       fmaf(q4.y, k4.y,
                       fmaf(q4.z, k4.z,
                       fmaf(q4.w, k4.w, s[i]))));
            }
        }

        // ---- scale + causal mask + online softmax ----
        float mt = -1e30f;
        const bool diag = (jt == qt);
        #pragma unroll
        for (int i = 0; i < 16; i++) {
            s[i] *= 0.125f;                       // 1/sqrt(64)
            if (diag && (g + 4*i) > r) s[i] = -1e30f;
            mt = fmaxf(mt, s[i]);
        }
        mt = fmaxf(mt, __shfl_xor_sync(0xffffffffu, mt, 1));
        mt = fmaxf(mt, __shfl_xor_sync(0xffffffffu, mt, 2));
        const float m_new = fmaxf(m_run, mt);
        const float alpha = __expf(m_run - m_new);

        float psum = 0.f;
        #pragma unroll
        for (int i = 0; i < 16; i++) {
            const float p = __expf(s[i] - m_new);
            psum += p;
            Ps[r*PADF + g + 4*i] = p;
        }
        psum += __shfl_xor_sync(0xffffffffu, psum, 1);
        psum += __shfl_xor_sync(0xffffffffu, psum, 2);
        l_run = l_run * alpha + psum;
        m_run = m_new;
        #pragma unroll
        for (int i = 0; i < 16; i++) acc[i] *= alpha;

        __syncwarp();   // Ps for row r written only by this warp's 4 threads

        // ---- acc += P[r][:] @ V ----
        #pragma unroll 4
        for (int j = 0; j < QT; j++) {
            const float p = Ps[r*PADF + j];
            #pragma unroll
            for (int mI = 0; mI < 4; mI++) {
                const float4 v4 = *(const float4*)(Vs + j*PADF + (g + 4*mI)*4);
                acc[mI*4+0] = fmaf(p, v4.x, acc[mI*4+0]);
                acc[mI*4+1] = fmaf(p, v4.y, acc[mI*4+1]);
                acc[mI*4+2] = fmaf(p, v4.z, acc[mI*4+2]);
                acc[mI*4+3] = fmaf(p, v4.w, acc[mI*4+3]);
            }
        }
    }

    const float inv = 1.f / l_run;
    float* op = g_vals + base + (size_t)(q0 + r) * D_DIM;
    #pragma unroll
    for (int mI = 0; mI < 4; mI++) {
        float4 o;
        o.x = acc[mI*4+0]*inv; o.y = acc[mI*4+1]*inv;
        o.z = acc[mI*4+2]*inv; o.w = acc[mI*4+3]*inv;
        *(float4*)(op + (g + 4*mI)*4) = o;
    }
}

// ---------------------------------------------------------------------------
// kernel_launch
// inputs: x, mask, Wq, bq, Wk, bk, Wv, bv, Wo, bo   (mask ignored; causal known)
// ---------------------------------------------------------------------------
extern "C" void kernel_launch(void* const* d_in, const int* in_sizes, int n_in,
                              void* d_out, int out_size)
{
    (void)in_sizes; (void)n_in; (void)out_size;
    const float* x  = (const float*)d_in[0];
    const float* Wq = (const float*)d_in[2];
    const float* bq = (const float*)d_in[3];
    const float* Wk = (const float*)d_in[4];
    const float* bk = (const float*)d_in[5];
    const float* Wv = (const float*)d_in[6];
    const float* bv = (const float*)d_in[7];
    const float* Wo = (const float*)d_in[8];
    const float* bo = (const float*)d_in[9];
    float* out = (float*)d_out;

    float *qp, *kp, *vp, *valsp;
    cudaGetSymbolAddress((void**)&qp,    g_q);
    cudaGetSymbolAddress((void**)&kp,    g_k);
    cudaGetSymbolAddress((void**)&vp,    g_v);
    cudaGetSymbolAddress((void**)&valsp, g_vals);

    cudaFuncSetAttribute(attn_kernel,
                         cudaFuncAttributeMaxDynamicSharedMemorySize, ATTN_SMEM);

    dim3 blk(256);
    dim3 gP(D_DIM/128, NROWS/128);         // (8, 64)
    sgemm_nt_bias<<<gP, blk>>>(x, Wq, bq, qp, NROWS, D_DIM, D_DIM);
    sgemm_nt_bias<<<gP, blk>>>(x, Wk, bk, kp, NROWS, D_DIM, D_DIM);
    sgemm_nt_bias<<<gP, blk>>>(x, Wv, bv, vp, NROWS, D_DIM, D_DIM);

    dim3 gA(S_LEN/QT, B_SZ*NH);            // (32, 64)
    attn_kernel<<<gA, blk, ATTN_SMEM>>>();

    sgemm_nt_bias<<<gP, blk>>>(valsp, Wo, bo, out, NROWS, D_DIM, D_DIM);
}